// round 9
// baseline (speedup 1.0000x reference)
#include <cuda_runtime.h>
#include <cuda_bf16.h>

// RAM multi-step transformer — round-6/8 structure (best: 33.3us), plus
// .L2::64B fetch-granularity qualifier on every random table load: each
// lookup needs 4B; default behavior measures as a full 128B line fill per
// miss (~98B/lookup of DRAM traffic). L2::64B requests half-line fills.
//
// x: (256,1024) i32 | conn_in: (2048,16) | conn_state: (1024,16) | conn_out: (512,16)
// mem_in: (2048,65536) f32 | mem_state: (1024,65536) f32 | mem_out: (512,65536) f32
// out: (256,512) f32

#define BATCH 256
#define IN_BITS 1024
#define N_IN 2048
#define N_ST 1024
#define N_OUT 512
#define TBL 65536
#define MAX_ITERS 4
#define THREADS 256

__device__ __forceinline__ unsigned long long mk_policy_pin() {
    unsigned long long pol;
    asm("createpolicy.fractional.L2::evict_last.b64 %0, 1.0;" : "=l"(pol));
    return pol;
}
__device__ __forceinline__ unsigned long long mk_policy_state() {
    unsigned long long pol;
    asm("createpolicy.fractional.L2::evict_last.L2::evict_first.b64 %0, 0.25;" : "=l"(pol));
    return pol;
}
// Table load: streaming-friendly cache hint + 64B L2 fetch granularity.
__device__ __forceinline__ float ld_tbl64(const float* p, unsigned long long pol) {
    float v;
    asm("ld.global.nc.L2::cache_hint.L2::64B.f32 %0, [%1], %2;"
        : "=f"(v) : "l"(p), "l"(pol));
    return v;
}

// 16-bit address from packed bit-words in shared memory.
__device__ __forceinline__ unsigned gather16(const unsigned* __restrict__ sw,
                                             int4 c0, int4 c1, int4 c2, int4 c3) {
    unsigned a = 0;
    a |= ((sw[c0.x >> 5] >> (c0.x & 31)) & 1u) << 0;
    a |= ((sw[c0.y >> 5] >> (c0.y & 31)) & 1u) << 1;
    a |= ((sw[c0.z >> 5] >> (c0.z & 31)) & 1u) << 2;
    a |= ((sw[c0.w >> 5] >> (c0.w & 31)) & 1u) << 3;
    a |= ((sw[c1.x >> 5] >> (c1.x & 31)) & 1u) << 4;
    a |= ((sw[c1.y >> 5] >> (c1.y & 31)) & 1u) << 5;
    a |= ((sw[c1.z >> 5] >> (c1.z & 31)) & 1u) << 6;
    a |= ((sw[c1.w >> 5] >> (c1.w & 31)) & 1u) << 7;
    a |= ((sw[c2.x >> 5] >> (c2.x & 31)) & 1u) << 8;
    a |= ((sw[c2.y >> 5] >> (c2.y & 31)) & 1u) << 9;
    a |= ((sw[c2.z >> 5] >> (c2.z & 31)) & 1u) << 10;
    a |= ((sw[c2.w >> 5] >> (c2.w & 31)) & 1u) << 11;
    a |= ((sw[c3.x >> 5] >> (c3.x & 31)) & 1u) << 12;
    a |= ((sw[c3.y >> 5] >> (c3.y & 31)) & 1u) << 13;
    a |= ((sw[c3.z >> 5] >> (c3.z & 31)) & 1u) << 14;
    a |= ((sw[c3.w >> 5] >> (c3.w & 31)) & 1u) << 15;
    return a;
}

__global__ __launch_bounds__(THREADS, 2)
void ram_multistep_kernel(
    const int* __restrict__ x,
    const int4* __restrict__ conn_in,
    const int4* __restrict__ conn_state,
    const int4* __restrict__ conn_out,
    const float* __restrict__ mem_in,
    const float* __restrict__ mem_state,
    const float* __restrict__ mem_out,
    float* __restrict__ out)
{
    __shared__ unsigned sx[32];       // 1024 input bits packed
    __shared__ unsigned sbufA[96];    // [0,64) in-bits, [64,96) state bits
    __shared__ unsigned sbufB[96];    // double buffer

    const int b = blockIdx.x;
    const int tid = threadIdx.x;
    const int lane = tid & 31;
    const int warp = tid >> 5;        // 0..7

    const unsigned long long pol_pin   = mk_policy_pin();
    const unsigned long long pol_state = mk_policy_state();

    // ---- Pack x bits (coalesced, ballot) ----
    #pragma unroll
    for (int r = 0; r < 4; r++) {
        int bit = __ldg(x + b * IN_BITS + r * 256 + tid);
        unsigned w = __ballot_sync(0xFFFFFFFFu, bit != 0);
        if (lane == 0) sx[r * 8 + warp] = w;
    }
    if (tid < 32) sbufA[64 + tid] = 0u;    // initial state = 0 (read by iter 0)
    __syncthreads();

    // ---- Input layer: 2048 neurons, 8 per thread, addr batch then load batch ----
    {
        unsigned addr[8];
        #pragma unroll
        for (int r = 0; r < 8; r++) {
            int n = r * 256 + tid;
            const int4* c = conn_in + n * 4;
            int4 c0 = __ldg(c + 0), c1 = __ldg(c + 1), c2 = __ldg(c + 2), c3 = __ldg(c + 3);
            addr[r] = gather16(sx, c0, c1, c2, c3);
        }
        float v[8];
        #pragma unroll
        for (int r = 0; r < 8; r++) {
            int n = r * 256 + tid;
            v[r] = ld_tbl64(mem_in + (size_t)n * TBL + addr[r], pol_pin);
        }
        #pragma unroll
        for (int r = 0; r < 8; r++) {
            unsigned w = __ballot_sync(0xFFFFFFFFu, v[r] > 0.5f);
            if (lane == 0) { sbufA[r * 8 + warp] = w; sbufB[r * 8 + warp] = w; }
        }
    }
    __syncthreads();

    // ---- Recurrent state iterations: 4 per thread, double-buffered, 1 barrier/iter ----
    unsigned* cur = sbufA;
    unsigned* nxt = sbufB;
    for (int it = 0; it < MAX_ITERS; it++) {
        unsigned addr[4];
        #pragma unroll
        for (int k = 0; k < 4; k++) {
            int n = k * 256 + tid;
            const int4* c = conn_state + n * 4;
            int4 c0 = __ldg(c + 0), c1 = __ldg(c + 1), c2 = __ldg(c + 2), c3 = __ldg(c + 3);
            addr[k] = gather16(cur, c0, c1, c2, c3);
        }
        float v[4];
        #pragma unroll
        for (int k = 0; k < 4; k++) {
            int n = k * 256 + tid;
            v[k] = ld_tbl64(mem_state + (size_t)n * TBL + addr[k], pol_state);
        }
        #pragma unroll
        for (int k = 0; k < 4; k++) {
            unsigned w = __ballot_sync(0xFFFFFFFFu, v[k] > 0.5f);
            if (lane == 0) nxt[64 + k * 8 + warp] = w;   // disjoint from cur: no pre-barrier
        }
        __syncthreads();                 // nxt complete & visible
        unsigned* t = cur; cur = nxt; nxt = t;
    }

    // ---- Output layer: 512 neurons, 2 per thread (final state only) ----
    {
        unsigned addr[2];
        #pragma unroll
        for (int r = 0; r < 2; r++) {
            int n = r * 256 + tid;
            const int4* c = conn_out + n * 4;
            int4 c0 = __ldg(c + 0), c1 = __ldg(c + 1), c2 = __ldg(c + 2), c3 = __ldg(c + 3);
            addr[r] = gather16(cur, c0, c1, c2, c3);
        }
        #pragma unroll
        for (int r = 0; r < 2; r++) {
            int n = r * 256 + tid;
            out[b * N_OUT + n] = ld_tbl64(mem_out + (size_t)n * TBL + addr[r], pol_pin);
        }
    }
}

extern "C" void kernel_launch(void* const* d_in, const int* in_sizes, int n_in,
                              void* d_out, int out_size) {
    const int* x            = (const int*)d_in[0];
    const int4* conn_in     = (const int4*)d_in[1];
    const int4* conn_state  = (const int4*)d_in[2];
    const int4* conn_out    = (const int4*)d_in[3];
    const float* mem_in     = (const float*)d_in[4];
    const float* mem_state  = (const float*)d_in[5];
    const float* mem_out    = (const float*)d_in[6];
    float* out = (float*)d_out;

    ram_multistep_kernel<<<BATCH, THREADS>>>(x, conn_in, conn_state, conn_out,
                                             mem_in, mem_state, mem_out, out);
}